// round 12
// baseline (speedup 1.0000x reference)
#include <cuda_runtime.h>
#include <cuda_bf16.h>
#include <math.h>
#include <stdint.h>

// Problem constants
#define B_  8
#define L_  2050
#define D_  320
#define M1  (B_ * L_)   // 16400
#define LMAIN 2048      // main GEMM2 region (16x128); rim handled by strip kernels

// ---------------------------------------------------------------------------
// Device-global scratch (allocation-free rule)
// ---------------------------------------------------------------------------
__device__ __nv_bfloat16 g_xh[(size_t)M1 * D_];
__device__ __nv_bfloat16 g_xl[(size_t)M1 * D_];
__device__ __nv_bfloat16 g_wth[D_ * D_];   // W transposed: [e][k]
__device__ __nv_bfloat16 g_wtl[D_ * D_];
__device__ __nv_bfloat16 g_xwh[(size_t)M1 * D_];
__device__ __nv_bfloat16 g_xwl[(size_t)M1 * D_];

// ---------------------------------------------------------------------------
// Split helpers
// ---------------------------------------------------------------------------
__device__ __forceinline__ void split_bf16(float v, __nv_bfloat16& h, __nv_bfloat16& l) {
    h = __float2bfloat16(v);
    l = __float2bfloat16(v - __bfloat162float(h));
}

__global__ void split_all_kernel(const float* __restrict__ x, const float* __restrict__ W) {
    int i = blockIdx.x * blockDim.x + threadIdx.x;
    const int n4 = M1 * D_ / 4;
    if (i < n4) {
        float4 v = ((const float4*)x)[i];
        __nv_bfloat16 h[4], l[4];
        float vs[4] = {v.x, v.y, v.z, v.w};
#pragma unroll
        for (int j = 0; j < 4; ++j) split_bf16(vs[j], h[j], l[j]);
        __nv_bfloat162* ph = (__nv_bfloat162*)g_xh;
        __nv_bfloat162* pl = (__nv_bfloat162*)g_xl;
        ph[2 * i + 0] = __nv_bfloat162{h[0], h[1]};
        ph[2 * i + 1] = __nv_bfloat162{h[2], h[3]};
        pl[2 * i + 0] = __nv_bfloat162{l[0], l[1]};
        pl[2 * i + 1] = __nv_bfloat162{l[2], l[3]};
    }
    if (i < D_ * D_) {
        int k = i / D_, e = i % D_;
        __nv_bfloat16 h, l;
        split_bf16(W[i], h, l);
        g_wth[e * D_ + k] = h;
        g_wtl[e * D_ + k] = l;
    }
}

// ---------------------------------------------------------------------------
// MMA / ldmatrix / cp.async primitives
// ---------------------------------------------------------------------------
__device__ __forceinline__ void cpasync16(uint32_t dst, const void* src, bool valid) {
    int sz = valid ? 16 : 0;
    asm volatile("cp.async.cg.shared.global [%0], [%1], 16, %2;\n"
                 :: "r"(dst), "l"(src), "r"(sz));
}
__device__ __forceinline__ void cp_commit() { asm volatile("cp.async.commit_group;\n"); }
template <int N>
__device__ __forceinline__ void cp_wait() { asm volatile("cp.async.wait_group %0;\n" :: "n"(N)); }

__device__ __forceinline__ void ldsm4(uint32_t& r0, uint32_t& r1, uint32_t& r2, uint32_t& r3, uint32_t addr) {
    asm volatile("ldmatrix.sync.aligned.m8n8.x4.shared.b16 {%0,%1,%2,%3}, [%4];\n"
                 : "=r"(r0), "=r"(r1), "=r"(r2), "=r"(r3) : "r"(addr));
}
__device__ __forceinline__ void mma16816(float* c, const uint32_t* a, const uint32_t* b) {
    asm volatile("mma.sync.aligned.m16n8k16.row.col.f32.bf16.bf16.f32 "
                 "{%0,%1,%2,%3}, {%4,%5,%6,%7}, {%8,%9}, {%0,%1,%2,%3};\n"
                 : "+f"(c[0]), "+f"(c[1]), "+f"(c[2]), "+f"(c[3])
                 : "r"(a[0]), "r"(a[1]), "r"(a[2]), "r"(a[3]), "r"(b[0]), "r"(b[1]));
}

__device__ __forceinline__ float fast_sigmoid(float v) {
    return __fdividef(1.0f, 1.0f + __expf(-v));
}

// ---------------------------------------------------------------------------
// GEMM — 3-stage ring, swizzled 64B rows
// BM fixed 128; BN templated: 128 for GEMM2 (guard-free), 64 for GEMM1
// ---------------------------------------------------------------------------
#define BM 128
#define BK 32
#define ROWB 64
#define A_BYTES (128 * ROWB)
#define NSTAGE 3

__device__ __forceinline__ uint32_t swz(int row, int seg) {
    return (uint32_t)(row * ROWB + ((seg ^ ((row >> 1) & 3)) << 4));
}

template <int BNT> struct Geom {
    static constexpr int B_BYTES = BNT * ROWB;
    static constexpr int STAGE_BYTES = 2 * A_BYTES + 2 * B_BYTES;
    static constexpr int OFF_AH = 0;
    static constexpr int OFF_AL = A_BYTES;
    static constexpr int OFF_BH = 2 * A_BYTES;
    static constexpr int OFF_BL = 2 * A_BYTES + B_BYTES;
    static constexpr int SMEM = NSTAGE * STAGE_BYTES;
    static constexpr int NI = BNT / 32;
    static constexpr int P  = BNT / 64;
};

// SIG=false: GEMM1 xW = x @ W -> split to g_xwh/l (BNT=64, guarded, M=M1 N=320)
// SIG=true : GEMM2 out = sigmoid(xW @ x^T + b) over [0,2048)^2 (guard-free)
template <bool SIG, int BNT>
__global__ __launch_bounds__(256, 2)
void gemm_bf16x3(const float* __restrict__ bias, float* __restrict__ Out)
{
    using G = Geom<BNT>;
    extern __shared__ char smem[];
    const uint32_t sbase = (uint32_t)__cvta_generic_to_shared(smem);

    const int M = SIG ? LMAIN : M1;
    const int N = SIG ? LMAIN : D_;

    const __nv_bfloat16* Ah = SIG ? g_xwh : g_xh;
    const __nv_bfloat16* Al = SIG ? g_xwl : g_xl;
    const __nv_bfloat16* Bh = SIG ? g_xh  : g_wth;
    const __nv_bfloat16* Bl = SIG ? g_xl  : g_wtl;
    if (SIG) {
        size_t off = (size_t)blockIdx.z * L_ * D_;
        Ah += off; Al += off; Bh += off; Bl += off;
    }

    const int m0 = blockIdx.y * BM;
    const int n0 = blockIdx.x * BNT;
    const int tid = threadIdx.x;
    const int lane = tid & 31;
    const int wid = tid >> 5;
    const int wm = (wid >> 2) * 64;
    const int wn = (wid & 3) * (BNT / 4);
    const int gid = lane >> 2, tig = lane & 3;

    float acc[4][G::NI][4];
#pragma unroll
    for (int i = 0; i < 4; ++i)
#pragma unroll
        for (int j = 0; j < G::NI; ++j)
#pragma unroll
            for (int f = 0; f < 4; ++f) acc[i][j][f] = 0.f;

    const int a_m = wm + ((lane >> 3) & 1) * 8 + (lane & 7);
    const int a_s = (lane >> 4) & 1;
    const int b_n = wn + ((lane >> 4) & 1) * 8 + (lane & 7);
    const int b_s = (lane >> 3) & 1;
    const int a_swb = (a_m >> 1) & 3;
    const int b_swb = (b_n >> 1) & 3;

    auto load_stage = [&](int kt, int s) {
        const int k0 = kt * BK;
        const uint32_t sb = sbase + s * G::STAGE_BYTES;
#pragma unroll
        for (int h = 0; h < 2; ++h) {            // A: 512 slots
            int c = tid + h * 256;
            int row = c >> 2, seg = c & 3;
            bool av = SIG ? true : ((m0 + row) < M);   // GEMM2: statically valid
            size_t aoff = (size_t)((SIG || av) ? m0 + row : 0) * D_ + k0 + seg * 8;
            uint32_t sm = swz(row, seg);
            cpasync16(sb + G::OFF_AH + sm, Ah + aoff, av);
            cpasync16(sb + G::OFF_AL + sm, Al + aoff, av);
        }
#pragma unroll
        for (int h = 0; h < BNT / 64; ++h) {     // B: BNT*4 slots
            int c = tid + h * 256;
            int row = c >> 2, seg = c & 3;
            bool bv = SIG ? true : ((n0 + row) < N);
            size_t boff = (size_t)((SIG || bv) ? n0 + row : 0) * D_ + k0 + seg * 8;
            uint32_t sm = swz(row, seg);
            cpasync16(sb + G::OFF_BH + sm, Bh + boff, bv);
            cpasync16(sb + G::OFF_BL + sm, Bl + boff, bv);
        }
        cp_commit();
    };

    const int KT = D_ / BK;   // 10
    load_stage(0, 0);
    load_stage(1, 1);

    int cbuf = 0, lbuf = 2;

    for (int kt = 0; kt < KT; ++kt) {
        if (kt + 1 < KT) cp_wait<1>();
        else             cp_wait<0>();
        __syncthreads();

        const uint32_t sb = sbase + cbuf * G::STAGE_BYTES;
#pragma unroll
        for (int ks = 0; ks < 2; ++ks) {
            const uint32_t sxa = (uint32_t)(((ks * 2 + a_s) ^ a_swb) << 4);
            const uint32_t sxb = (uint32_t)(((ks * 2 + b_s) ^ b_swb) << 4);

            uint32_t ah[4][4], al[4][4], bh[G::P][4], bl[G::P][4];
#pragma unroll
            for (int mi = 0; mi < 4; ++mi) {
                uint32_t adr = sb + G::OFF_AH + (uint32_t)((a_m + mi * 16) * ROWB) + sxa;
                ldsm4(ah[mi][0], ah[mi][1], ah[mi][2], ah[mi][3], adr);
            }
#pragma unroll
            for (int p = 0; p < G::P; ++p) {
                uint32_t adr = sb + G::OFF_BH + (uint32_t)((b_n + p * 16) * ROWB) + sxb;
                ldsm4(bh[p][0], bh[p][1], bh[p][2], bh[p][3], adr);
            }
#pragma unroll
            for (int mi = 0; mi < 4; ++mi)
#pragma unroll
                for (int ni = 0; ni < G::NI; ++ni)
                    mma16816(acc[mi][ni], ah[mi], &bh[ni >> 1][(ni & 1) * 2]);

            if (ks == 0 && kt + 2 < KT) load_stage(kt + 2, lbuf);

#pragma unroll
            for (int p = 0; p < G::P; ++p) {
                uint32_t adr = sb + G::OFF_BL + (uint32_t)((b_n + p * 16) * ROWB) + sxb;
                ldsm4(bl[p][0], bl[p][1], bl[p][2], bl[p][3], adr);
            }
#pragma unroll
            for (int mi = 0; mi < 4; ++mi)
#pragma unroll
                for (int ni = 0; ni < G::NI; ++ni)
                    mma16816(acc[mi][ni], ah[mi], &bl[ni >> 1][(ni & 1) * 2]);

#pragma unroll
            for (int mi = 0; mi < 4; ++mi) {
                uint32_t adr = sb + G::OFF_AL + (uint32_t)((a_m + mi * 16) * ROWB) + sxa;
                ldsm4(al[mi][0], al[mi][1], al[mi][2], al[mi][3], adr);
            }
#pragma unroll
            for (int mi = 0; mi < 4; ++mi)
#pragma unroll
                for (int ni = 0; ni < G::NI; ++ni)
                    mma16816(acc[mi][ni], al[mi], &bh[ni >> 1][(ni & 1) * 2]);
        }

        cbuf = (cbuf == 2) ? 0 : cbuf + 1;
        lbuf = (lbuf == 2) ? 0 : lbuf + 1;
    }

    // -------------------- epilogue --------------------
    if (SIG) {
        const float bv = bias[0];
        float* Cb = Out + (size_t)blockIdx.z * L_ * L_;
#pragma unroll
        for (int mi = 0; mi < 4; ++mi)
#pragma unroll
            for (int half = 0; half < 2; ++half) {
                int gm = m0 + wm + mi * 16 + gid + half * 8;   // always < 2048
#pragma unroll
                for (int ni = 0; ni < G::NI; ++ni) {
                    int gn = n0 + wn + ni * 8 + 2 * tig;       // always < 2048
                    float2 r;
                    r.x = fast_sigmoid(acc[mi][ni][half * 2 + 0] + bv);
                    r.y = fast_sigmoid(acc[mi][ni][half * 2 + 1] + bv);
                    *(float2*)&Cb[(size_t)gm * L_ + gn] = r;
                }
            }
    } else {
#pragma unroll
        for (int mi = 0; mi < 4; ++mi)
#pragma unroll
            for (int half = 0; half < 2; ++half) {
                int gm = m0 + wm + mi * 16 + gid + half * 8;
                if (gm >= M) continue;
#pragma unroll
                for (int ni = 0; ni < G::NI; ++ni) {
                    int gn = n0 + wn + ni * 8 + 2 * tig;
                    if (gn >= N) continue;
                    float v0 = acc[mi][ni][half * 2 + 0];
                    float v1 = acc[mi][ni][half * 2 + 1];
                    __nv_bfloat16 h0, l0, h1, l1;
                    split_bf16(v0, h0, l0);
                    split_bf16(v1, h1, l1);
                    size_t idx = (size_t)gm * D_ + gn;
                    *(__nv_bfloat162*)&g_xwh[idx] = __nv_bfloat162{h0, h1};
                    *(__nv_bfloat162*)&g_xwl[idx] = __nv_bfloat162{l0, l1};
                }
            }
    }
}

// ---------------------------------------------------------------------------
// Rim strips: out[b,i,j] for j in {2048,2049} (all i), and i in {2048,2049}
// (j < 2048). fp32 reconstruction from split pairs; warp per output-pair.
// ---------------------------------------------------------------------------
__global__ void strip_cols(const float* __restrict__ bias, float* __restrict__ Out) {
    const int b = blockIdx.y;
    const int tid = threadIdx.x, lane = tid & 31, w = tid >> 5;
    const int i = blockIdx.x * 8 + w;
    __shared__ float xj[2][D_];
    for (int t = tid; t < 2 * D_; t += 256) {
        int c = t / D_, k = t % D_;
        size_t idx = ((size_t)b * L_ + LMAIN + c) * D_ + k;
        xj[c][k] = __bfloat162float(g_xh[idx]) + __bfloat162float(g_xl[idx]);
    }
    __syncthreads();
    if (i >= L_) return;
    size_t ar = ((size_t)b * L_ + i) * D_;
    float a0 = 0.f, a1 = 0.f;
#pragma unroll
    for (int k = lane; k < D_; k += 32) {
        float a = __bfloat162float(g_xwh[ar + k]) + __bfloat162float(g_xwl[ar + k]);
        a0 += a * xj[0][k];
        a1 += a * xj[1][k];
    }
#pragma unroll
    for (int o = 16; o; o >>= 1) {
        a0 += __shfl_xor_sync(0xFFFFFFFFu, a0, o);
        a1 += __shfl_xor_sync(0xFFFFFFFFu, a1, o);
    }
    if (lane == 0) {
        float bv = bias[0];
        size_t orow = ((size_t)b * L_ + i) * L_;
        Out[orow + LMAIN + 0] = fast_sigmoid(a0 + bv);
        Out[orow + LMAIN + 1] = fast_sigmoid(a1 + bv);
    }
}

__global__ void strip_rows(const float* __restrict__ bias, float* __restrict__ Out) {
    const int b = blockIdx.y;
    const int tid = threadIdx.x, lane = tid & 31, w = tid >> 5;
    const int j = blockIdx.x * 8 + w;
    __shared__ float xwi[2][D_];
    for (int t = tid; t < 2 * D_; t += 256) {
        int c = t / D_, k = t % D_;
        size_t idx = ((size_t)b * L_ + LMAIN + c) * D_ + k;
        xwi[c][k] = __bfloat162float(g_xwh[idx]) + __bfloat162float(g_xwl[idx]);
    }
    __syncthreads();
    if (j >= LMAIN) return;
    size_t br = ((size_t)b * L_ + j) * D_;
    float a0 = 0.f, a1 = 0.f;
#pragma unroll
    for (int k = lane; k < D_; k += 32) {
        float v = __bfloat162float(g_xh[br + k]) + __bfloat162float(g_xl[br + k]);
        a0 += v * xwi[0][k];
        a1 += v * xwi[1][k];
    }
#pragma unroll
    for (int o = 16; o; o >>= 1) {
        a0 += __shfl_xor_sync(0xFFFFFFFFu, a0, o);
        a1 += __shfl_xor_sync(0xFFFFFFFFu, a1, o);
    }
    if (lane == 0) {
        float bv = bias[0];
        Out[((size_t)b * L_ + LMAIN + 0) * L_ + j] = fast_sigmoid(a0 + bv);
        Out[((size_t)b * L_ + LMAIN + 1) * L_ + j] = fast_sigmoid(a1 + bv);
    }
}

// ---------------------------------------------------------------------------
extern "C" void kernel_launch(void* const* d_in, const int* in_sizes, int n_in,
                              void* d_out, int out_size)
{
    const float* x  = (const float*)d_in[0];   // (B, L, D)
    const float* W  = (const float*)d_in[1];   // (D, D)
    const float* bb = (const float*)d_in[2];   // (1,)
    float* out = (float*)d_out;                // (B, L, L)

    (void)cudaFuncSetAttribute(gemm_bf16x3<false, 64>,
                               cudaFuncAttributeMaxDynamicSharedMemorySize, Geom<64>::SMEM);
    (void)cudaFuncSetAttribute(gemm_bf16x3<true, 128>,
                               cudaFuncAttributeMaxDynamicSharedMemorySize, Geom<128>::SMEM);

    // 1) split x and W into bf16 hi/lo
    {
        int n4 = M1 * D_ / 4;
        split_all_kernel<<<(n4 + 255) / 256, 256>>>(x, W);
    }
    // 2) xW = x @ W
    {
        dim3 grid(D_ / 64, (M1 + BM - 1) / BM, 1);              // (5, 129)
        gemm_bf16x3<false, 64><<<grid, 256, Geom<64>::SMEM>>>(nullptr, nullptr);
    }
    // 3) rim strips (deps: xW, x) — cover j>=2048 (all i) and i>=2048 (j<2048)
    {
        dim3 gc((L_ + 7) / 8, B_);       // (257, 8)
        strip_cols<<<gc, 256>>>(bb, out);
        dim3 gr(LMAIN / 8, B_);          // (256, 8)
        strip_rows<<<gr, 256>>>(bb, out);
    }
    // 4) main GEMM2 over [0,2048)^2 — guard-free
    {
        dim3 grid(LMAIN / 128, LMAIN / 128, B_);                // (16, 16, 8)
        gemm_bf16x3<true, 128><<<grid, 256, Geom<128>::SMEM>>>(bb, out);
    }
}